// round 11
// baseline (speedup 1.0000x reference)
#include <cuda_runtime.h>
#include <cuda_fp16.h>
#include <cstdint>

// ElementUpdate: out[n,:] = h_prev[n,:] + W[z[n]] @ m_curr[n,:]
// N=16384, D=128, S=119, z sorted globally.
// R10: species-chunk scheduling. Scheduler kernel enumerates (species, <=64-row
// chunk) descriptors from the global sorted z. Main kernel: one CTA per
// (chunk, N-half): single species -> no masks, no segment loop, one fill, one
// barrier, straight fp16 m16n8k16 MMA. ~630 small CTAs, 3 CTAs/SM.

static constexpr int D = 128;
static constexpr int NSPEC = 119;
static constexpr int NT = 256;
static constexpr int HPAD = 136;           // half stride, conflict-free
static constexpr int HDR = 1024;
static constexpr int A_BYTES = 64 * HPAD * 2;   // 17408
static constexpr int W_BYTES = 64 * HPAD * 2;   // 17408
static constexpr int SMEM_BYTES = HDR + A_BYTES + W_BYTES;  // 35840 -> 3+ CTAs/SM
static constexpr int MAXC = 512;
static constexpr int GRID_MAIN = MAXC * 2;

__device__ int4 g_desc[MAXC];   // {row_start, nrows, species, 0}

__device__ __forceinline__ uint32_t pack_h2(float lo, float hi) {
    uint32_t r;
    asm("cvt.rn.f16x2.f32 %0, %1, %2;" : "=r"(r) : "f"(hi), "f"(lo));
    return r;
}

__device__ __forceinline__ void mma_f16(float* d, const uint32_t* a,
                                        uint32_t b0, uint32_t b1) {
    asm volatile(
        "mma.sync.aligned.m16n8k16.row.col.f32.f16.f16.f32 "
        "{%0,%1,%2,%3}, {%4,%5,%6,%7}, {%8,%9}, {%0,%1,%2,%3};"
        : "+f"(d[0]), "+f"(d[1]), "+f"(d[2]), "+f"(d[3])
        : "r"(a[0]), "r"(a[1]), "r"(a[2]), "r"(a[3]), "r"(b0), "r"(b1));
}

// ---------------- scheduler: build chunk descriptors ----------------
__global__ void sched_kernel(const int* __restrict__ z, int n) {
    extern __shared__ int sz[];               // n ints (64KB for 16384)
    __shared__ int sStart[NSPEC + 1];
    __shared__ int sNch[NSPEC];
    __shared__ int sOff[NSPEC + 1];
    const int tid = threadIdx.x;

    for (int i = tid; i < n; i += NT) sz[i] = z[i];
    __syncthreads();

    if (tid <= NSPEC) {
        // lower_bound(species tid) over sz[0..n)
        int lo = 0, hi = n;
        while (lo < hi) {
            int mid = (lo + hi) >> 1;
            if (sz[mid] < tid) lo = mid + 1; else hi = mid;
        }
        sStart[tid] = lo;                     // sStart[NSPEC] == n
    }
    __syncthreads();
    if (tid < NSPEC) sNch[tid] = (sStart[tid + 1] - sStart[tid] + 63) >> 6;
    __syncthreads();
    if (tid == 0) {
        int acc = 0;
        for (int s = 0; s < NSPEC; s++) { sOff[s] = acc; acc += sNch[s]; }
        sOff[NSPEC] = acc;
    }
    __syncthreads();
    if (tid < NSPEC) {
        int st = sStart[tid], cnt = sStart[tid + 1] - st;
        for (int j = 0; j < sNch[tid]; j++) {
            int r0 = st + 64 * j;
            int nr = min(64, cnt - 64 * j);
            g_desc[sOff[tid] + j] = make_int4(r0, nr, tid, 0);
        }
    }
    const int total = sOff[NSPEC];
    for (int i = total + tid; i < MAXC; i += NT)
        g_desc[i] = make_int4(0, 0, 0, 0);
}

// ---------------- main: one CTA per (chunk, N-half) ----------------
__global__ void __launch_bounds__(NT, 3)
element_update_kernel(const float* __restrict__ h_prev,
                      const float* __restrict__ m_curr,
                      const float* __restrict__ weight,
                      float* __restrict__ out) {
    extern __shared__ __align__(16) char smem[];
    const int tid = threadIdx.x;
    const int lane = tid & 31;
    const int wid = tid >> 5;

    const int4 dsc = g_desc[blockIdx.x >> 1];
    const int r0 = dsc.x, nr = dsc.y, s = dsc.z;
    if (nr == 0) return;
    const int N0 = (blockIdx.x & 1) * 64;

    __half* sA = (__half*)(smem + HDR);
    __half* sW = (__half*)(smem + HDR + A_BYTES);

    // ---- A fill: chunk rows -> fp16 (rows >= nr zeroed) ----
    #pragma unroll
    for (int j = 0; j < 8; j++) {
        int i = tid + j * NT;
        int r = i >> 5, c4 = (i & 31) << 2;
        uint2 u = make_uint2(0u, 0u);
        if (r < nr) {
            float4 v = *(const float4*)(m_curr + (size_t)(r0 + r) * D + c4);
            u.x = pack_h2(v.x, v.y);
            u.y = pack_h2(v.z, v.w);
        }
        *(uint2*)(sA + r * HPAD + c4) = u;
    }
    // ---- W fill: W[s] rows [N0, N0+64) -> fp16 ----
    {
        const float* wsrc = weight + (size_t)s * (D * D) + (size_t)N0 * D;
        #pragma unroll
        for (int j = 0; j < 8; j++) {
            int i = tid + j * NT;
            int r = i >> 5, c4 = (i & 31) << 2;
            float4 v = *(const float4*)(wsrc + (size_t)r * D + c4);
            uint2 u;
            u.x = pack_h2(v.x, v.y);
            u.y = pack_h2(v.z, v.w);
            *(uint2*)(sW + r * HPAD + c4) = u;
        }
    }
    __syncthreads();

    // ---- warp geometry: rows [16*wr,+16) x half-cols [32*wc,+32) ----
    const int wr = wid >> 1;     // 0..3
    const int wc = wid & 1;      // 0..1
    const int rlo = wr * 16;
    const int lr = lane >> 2;    // 0..7
    const int lc = lane & 3;     // 0..3

    float acc[4][4];
    #pragma unroll
    for (int nt = 0; nt < 4; nt++)
        #pragma unroll
        for (int j = 0; j < 4; j++) acc[nt][j] = 0.f;

    if (rlo < nr) {
        const __half* pA0 = sA + (rlo + lr) * HPAD + lc * 2;
        const __half* pA1 = pA0 + 8 * HPAD;
        const __half* pB0 = sW + (wc * 32 + lr) * HPAD + lc * 2;

        #pragma unroll
        for (int ks = 0; ks < 8; ks++) {
            const int k0 = ks * 16;
            uint32_t aF[4];
            aF[0] = *(const uint32_t*)(pA0 + k0);
            aF[1] = *(const uint32_t*)(pA1 + k0);
            aF[2] = *(const uint32_t*)(pA0 + k0 + 8);
            aF[3] = *(const uint32_t*)(pA1 + k0 + 8);
            #pragma unroll
            for (int nt = 0; nt < 4; nt++) {
                const __half* pB = pB0 + nt * (8 * HPAD) + k0;
                uint32_t b0 = *(const uint32_t*)(pB);
                uint32_t b1 = *(const uint32_t*)(pB + 8);
                mma_f16(acc[nt], aF, b0, b1);
            }
        }
    }

    // ---- epilogue: acc + h_prev -> out (row-guarded, coalesced float2) ----
    #pragma unroll
    for (int h = 0; h < 2; h++) {
        const int rl = rlo + 8 * h + lr;
        if (rl < nr) {
            const int r = r0 + rl;
            const float* hp = h_prev + (size_t)r * D;
            float* op = out + (size_t)r * D;
            #pragma unroll
            for (int nt = 0; nt < 4; nt++) {
                const int c = N0 + wc * 32 + 8 * nt + lc * 2;
                float2 hv = *(const float2*)(hp + c);
                float2 o;
                o.x = hv.x + acc[nt][2 * h + 0];
                o.y = hv.y + acc[nt][2 * h + 1];
                *(float2*)(op + c) = o;
            }
        }
    }
}

extern "C" void kernel_launch(void* const* d_in, const int* in_sizes, int n_in,
                              void* d_out, int out_size) {
    const float* h_prev     = (const float*)d_in[0];
    const float* m_curr     = (const float*)d_in[1];
    const int*   atom_types = (const int*)d_in[2];
    const float* weight     = (const float*)d_in[3];
    float* out = (float*)d_out;

    int n_nodes = in_sizes[2];           // 16384

    static bool attr_done = false;
    if (!attr_done) {
        cudaFuncSetAttribute(sched_kernel,
                             cudaFuncAttributeMaxDynamicSharedMemorySize,
                             n_nodes * (int)sizeof(int));
        cudaFuncSetAttribute(element_update_kernel,
                             cudaFuncAttributeMaxDynamicSharedMemorySize, SMEM_BYTES);
        attr_done = true;
    }

    sched_kernel<<<1, NT, n_nodes * sizeof(int)>>>(atom_types, n_nodes);
    element_update_kernel<<<GRID_MAIN, NT, SMEM_BYTES>>>(h_prev, m_curr, weight, out);
}

// round 12
// speedup vs baseline: 1.2973x; 1.2973x over previous
#include <cuda_runtime.h>
#include <cuda_fp16.h>
#include <cstdint>

// ElementUpdate: out[n,:] = h_prev[n,:] + W[z[n]] @ m_curr[n,:]
// N=16384, D=128, S=119, z sorted.
// R12: R9 (fp16 m16n8k16, best 13.1us) + forced 3 CTAs/SM residency via
// __launch_bounds__(256,3). 24 warps/SM so fill/barrier phases of one CTA are
// covered by the other two. Everything else identical to R9.

static constexpr int D = 128;
static constexpr int TILE_M = 64;
static constexpr int NT = 256;
static constexpr int HPAD = 136;               // half-stride: 272B row, conflict-free
static constexpr int HDR = 1024;
static constexpr int A_BYTES = TILE_M * HPAD * 2;   // 17408
static constexpr int W_BYTES = D * HPAD * 2;        // 34816
static constexpr int SMEM_BYTES = HDR + A_BYTES + W_BYTES;  // 53248 (x3 = 156KB ok)

__device__ __forceinline__ uint32_t pack_h2(float lo, float hi) {
    uint32_t r;
    asm("cvt.rn.f16x2.f32 %0, %1, %2;" : "=r"(r) : "f"(hi), "f"(lo));
    return r;
}

__device__ __forceinline__ void mma_f16(float* d, const uint32_t* a,
                                        uint32_t b0, uint32_t b1) {
    asm volatile(
        "mma.sync.aligned.m16n8k16.row.col.f32.f16.f16.f32 "
        "{%0,%1,%2,%3}, {%4,%5,%6,%7}, {%8,%9}, {%0,%1,%2,%3};"
        : "+f"(d[0]), "+f"(d[1]), "+f"(d[2]), "+f"(d[3])
        : "r"(a[0]), "r"(a[1]), "r"(a[2]), "r"(a[3]), "r"(b0), "r"(b1));
}

__global__ void __launch_bounds__(NT, 3)
element_update_kernel(const float* __restrict__ h_prev,
                      const float* __restrict__ m_curr,
                      const int* __restrict__ atom_types,
                      const float* __restrict__ weight,
                      float* __restrict__ out) {
    extern __shared__ __align__(16) char smem[];
    const int tid = threadIdx.x;
    const int lane = tid & 31;
    const int wid = tid >> 5;
    const int R0 = blockIdx.x * TILE_M;

    int* sCnt  = (int*)(smem + 0);
    int* sNseg = (int*)(smem + 32);
    int* sRow  = (int*)(smem + 64);     // up to TILE_M+1
    int* sSpec = (int*)(smem + 384);    // up to TILE_M
    __half* sA = (__half*)(smem + HDR);
    __half* sW = (__half*)(smem + HDR + A_BYTES);

    // ---- species-segment scan over TILE_M sorted z values (warps 0-1) ----
    bool bd = false; int wpre = 0, zr = 0;
    if (tid < TILE_M) {
        zr = atom_types[R0 + tid];
        int zp = (tid == 0) ? -1 : atom_types[R0 + tid - 1];
        bd = (zp != zr);
        unsigned msk = __ballot_sync(0xffffffffu, bd);
        wpre = __popc(msk & ((1u << lane) - 1u));
        if (lane == 0) sCnt[wid] = __popc(msk);
    }

    // ---- A fill (m_curr -> fp16) + W[s0] prefill, overlapped with scan ----
    const int s0 = atom_types[R0];
    #pragma unroll
    for (int j = 0; j < 8; j++) {
        int i = tid + j * NT;
        int r = i >> 5, c4 = (i & 31) << 2;
        float4 v = *(const float4*)(m_curr + (size_t)(R0 + r) * D + c4);
        uint2 u;
        u.x = pack_h2(v.x, v.y);
        u.y = pack_h2(v.z, v.w);
        *(uint2*)(sA + r * HPAD + c4) = u;
    }
    {
        const float* wsrc = weight + (size_t)s0 * (D * D);
        #pragma unroll
        for (int j = 0; j < 16; j++) {
            int i = tid + j * NT;
            int r = i >> 5, c4 = (i & 31) << 2;
            float4 v = *(const float4*)(wsrc + (size_t)r * D + c4);
            uint2 u;
            u.x = pack_h2(v.x, v.y);
            u.y = pack_h2(v.z, v.w);
            *(uint2*)(sW + r * HPAD + c4) = u;
        }
    }
    __syncthreads();
    if (tid == 0) {
        int c0 = sCnt[0], c1 = sCnt[1];
        sCnt[2] = c0;
        *sNseg = c0 + c1;
        sRow[c0 + c1] = TILE_M;
    }
    __syncthreads();
    if (tid < TILE_M && bd) {
        int i = (wid ? sCnt[2] : 0) + wpre;
        sRow[i] = tid;
        sSpec[i] = zr;
    }
    __syncthreads();
    const int nseg = *sNseg;

    // ---- warp geometry: rows [16*wr,+16) x cols [64*wc,+64) ----
    const int wr = wid >> 1;     // 0..3
    const int wc = wid & 1;      // 0..1
    const int rlo = wr * 16;
    const int lr = lane >> 2;    // 0..7
    const int lc = lane & 3;     // 0..3

    float acc[8][4];
    #pragma unroll
    for (int nt = 0; nt < 8; nt++)
        #pragma unroll
        for (int j = 0; j < 4; j++) acc[nt][j] = 0.f;

    // fragment base pointers (halves). k16-step ks: A k = ks*16 + lc*2 (+8 for a2/a3)
    const __half* pA0 = sA + (rlo + lr) * HPAD + lc * 2;          // row r
    const __half* pA1 = pA0 + 8 * HPAD;                           // row r+8
    const __half* pB0 = sW + (wc * 64 + lr) * HPAD + lc * 2;      // B: n = base+lr

    for (int seg = 0; seg < nseg; seg++) {
        const int a = sRow[seg];
        const int b = sRow[seg + 1];

        if (seg > 0) {
            const int s = sSpec[seg];
            __syncthreads();   // previous segment's compute done before W overwrite
            const float* wsrc = weight + (size_t)s * (D * D);
            #pragma unroll
            for (int j = 0; j < 16; j++) {
                int i = tid + j * NT;
                int r = i >> 5, c4 = (i & 31) << 2;
                float4 v = *(const float4*)(wsrc + (size_t)r * D + c4);
                uint2 u;
                u.x = pack_h2(v.x, v.y);
                u.y = pack_h2(v.z, v.w);
                *(uint2*)(sW + r * HPAD + c4) = u;
            }
            __syncthreads();
        }

        if (b > rlo && a < rlo + 16) {
            const int r0 = rlo + lr;
            const uint32_t am0 = (r0 >= a && r0 < b) ? 0xffffffffu : 0u;
            const uint32_t am1 = (r0 + 8 >= a && r0 + 8 < b) ? 0xffffffffu : 0u;

            #pragma unroll
            for (int ks = 0; ks < 8; ks++) {
                const int k0 = ks * 16;
                uint32_t aF[4];
                aF[0] = *(const uint32_t*)(pA0 + k0) & am0;
                aF[1] = *(const uint32_t*)(pA1 + k0) & am1;
                aF[2] = *(const uint32_t*)(pA0 + k0 + 8) & am0;
                aF[3] = *(const uint32_t*)(pA1 + k0 + 8) & am1;
                #pragma unroll
                for (int nt = 0; nt < 8; nt++) {
                    const __half* pB = pB0 + nt * (8 * HPAD) + k0;
                    uint32_t b0 = *(const uint32_t*)(pB);
                    uint32_t b1 = *(const uint32_t*)(pB + 8);
                    mma_f16(acc[nt], aF, b0, b1);
                }
            }
        }
    }

    // ---- epilogue: acc + h_prev -> out (coalesced float2, 32B sectors) ----
    #pragma unroll
    for (int h = 0; h < 2; h++) {
        const int r = R0 + rlo + 8 * h + lr;
        const float* hp = h_prev + (size_t)r * D;
        float* op = out + (size_t)r * D;
        #pragma unroll
        for (int nt = 0; nt < 8; nt++) {
            const int c = wc * 64 + 8 * nt + lc * 2;
            float2 hv = *(const float2*)(hp + c);
            float2 o;
            o.x = hv.x + acc[nt][2 * h + 0];
            o.y = hv.y + acc[nt][2 * h + 1];
            *(float2*)(op + c) = o;
        }
    }
}

extern "C" void kernel_launch(void* const* d_in, const int* in_sizes, int n_in,
                              void* d_out, int out_size) {
    const float* h_prev     = (const float*)d_in[0];
    const float* m_curr     = (const float*)d_in[1];
    const int*   atom_types = (const int*)d_in[2];
    const float* weight     = (const float*)d_in[3];
    float* out = (float*)d_out;

    int n_nodes = in_sizes[0] / D;   // 16384
    int grid = n_nodes / TILE_M;     // 256

    cudaFuncSetAttribute(element_update_kernel,
                         cudaFuncAttributeMaxDynamicSharedMemorySize, SMEM_BYTES);
    element_update_kernel<<<grid, NT, SMEM_BYTES>>>(h_prev, m_curr, atom_types,
                                                    weight, out);
}